// round 5
// baseline (speedup 1.0000x reference)
#include <cuda_runtime.h>
#include <cstdint>

// Problem constants
#define NN   24
#define EE   96
#define BB   4
#define CC   8
#define HH   96
#define WW   96
#define KK   4
#define HW    (HH*WW)
#define CHW   (CC*HW)
#define BCHW  (BB*CHW)

// Padded activation scratch, ci-pair interleaved:
//   layout [g=100][pair=4][pos<PLANE][half=2], value(ci,pos) at
//   ((g*4 + (ci&3))*PLANE + pos)*2 + (ci>>2).  Zero border (never written).
#define PH 100
#define PW 100
#define PLANE (PH*PW)
#define NACT  (25*BB*4*PLANE*2)

// Conv-MMA tiling
#define SEGPX  640               // pixels per block (40 m16 tiles)
#define NSEG   15
#define TPW    5                 // m16 tiles per warp (8 warps)
#define WINF   944               // window positions per ci
#define PSTR2  1896              // pair stride in floats (>=2*WINF, ==8 mod 32)
#define BUFF   (4*PSTR2)         // 7584 floats per buffer
#define PAIR4  472               // float4s per pair window (944*2/4)
#define NBLK   (NSEG*BB*NN)      // 1440 conv blocks

__device__ __align__(16) float g_act[NACT];
__device__ int   g_off[NN + 1];
__device__ int   g_elist[EE];
__device__ float g_escale[EE];
__device__ float g_postsum[NN];
__device__ unsigned int g_done;

__device__ __forceinline__ uint32_t f2tf32(float v) {
    uint32_t r;
    asm("cvt.rna.tf32.f32 %0, %1;" : "=r"(r) : "f"(v));
    return r;
}

__device__ __forceinline__ void mma_tf32(float* d, uint32_t a0, uint32_t a1,
                                         uint32_t a2, uint32_t a3,
                                         uint32_t b0, uint32_t b1) {
    asm volatile(
        "mma.sync.aligned.m16n8k8.row.col.f32.tf32.tf32.f32 "
        "{%0,%1,%2,%3}, {%4,%5,%6,%7}, {%8,%9}, {%0,%1,%2,%3};"
        : "+f"(d[0]), "+f"(d[1]), "+f"(d[2]), "+f"(d[3])
        : "r"(a0), "r"(a1), "r"(a2), "r"(a3), "r"(b0), "r"(b1));
}

__device__ __forceinline__ void cpa16(uint32_t dst, const void* src) {
    asm volatile("cp.async.cg.shared.global [%0], [%1], 16;"
                 :: "r"(dst), "l"(src));
}
__device__ __forceinline__ uint32_t smem_u32(const void* p) {
    uint32_t a;
    asm("{ .reg .u64 t; cvta.to.shared.u64 t, %1; cvt.u32.u64 %0, t; }"
        : "=r"(a) : "l"(p));
    return a;
}

// ---------------------------------------------------------------------------
// Activation precompute (+ prep in block (0,0)). grid = (9, 800 planes).
// Writes sigmoid(states) tf32-rounded into the ci-pair interleaved scratch.
// ---------------------------------------------------------------------------
__global__ __launch_bounds__(256)
void act_prep_kernel(const float* __restrict__ states,
                     const int* __restrict__ dst,
                     const float* __restrict__ plast) {
    const int t = threadIdx.x;
    if (blockIdx.x == 0 && blockIdx.y == 0) {
        __shared__ int cnt[NN];
        __shared__ int fill[NN];
        if (t < NN) { cnt[t] = 0; g_postsum[t] = 0.0f; }
        __syncthreads();
        if (t < EE) atomicAdd(&cnt[dst[t]], 1);
        __syncthreads();
        if (t == 0) {
            int off = 0;
            for (int n = 0; n < NN; ++n) { g_off[n] = off; fill[n] = off; off += cnt[n]; }
            g_off[NN] = off;
        }
        __syncthreads();
        if (t < EE) {
            int d = dst[t];
            int pos = atomicAdd(&fill[d], 1);
            g_elist[pos] = t;
            int deg = cnt[d] > 0 ? cnt[d] : 1;
            g_escale[t] = plast[t] / (float)deg;
        }
    }
    const int plane = blockIdx.y;                 // (g*CC + ci), 0..799
    const int g = plane >> 3;
    const int ci = plane & 7;
    const int pair = ci & 3;
    const int half = ci >> 2;
    const int idx4 = blockIdx.x * 256 + t;        // 0..2303
    const int r = idx4 / 24;
    const int c4 = idx4 - r * 24;

    const float4 z4 = *reinterpret_cast<const float4*>(
        states + (size_t)plane * HW + r * WW + c4 * 4);

    float v0 = __uint_as_float(f2tf32(1.0f / (1.0f + __expf(-z4.x))));
    float v1 = __uint_as_float(f2tf32(1.0f / (1.0f + __expf(-z4.y))));
    float v2 = __uint_as_float(f2tf32(1.0f / (1.0f + __expf(-z4.z))));
    float v3 = __uint_as_float(f2tf32(1.0f / (1.0f + __expf(-z4.w))));

    float* op = g_act
        + (((size_t)(g * 4 + pair)) * PLANE + (r + 1) * PW + 1 + c4 * 4) * 2
        + half;
    op[0] = v0; op[2] = v1; op[4] = v2; op[6] = v3;
}

// ---------------------------------------------------------------------------
// Conv via warp MMA (tf32), LDS.64 interleaved fragments, double-buffered
// cp.async, fused plasticity. grid = (NSEG, B, N), 256 threads.
// ---------------------------------------------------------------------------
extern __shared__ float s_dyn[];

__global__ __launch_bounds__(256, 2)
void conv_mma_kernel(const float* __restrict__ weights,
                     const int* __restrict__ src,
                     const float* __restrict__ plast,
                     const int* __restrict__ dst,
                     float* __restrict__ out,
                     float* __restrict__ outp) {
    const int seg = blockIdx.x;
    const int b = blockIdx.y;
    const int n = blockIdx.z;
    const int qbase = seg * SEGPX;

    __shared__ float s_red[8];
    __shared__ int s_last;
    float* s_win = s_dyn;                          // [2][BUFF]
    const uint32_t s_win_u32 = smem_u32(s_win);

    const int t = threadIdx.x;
    const int w = t >> 5;
    const int l = t & 31;
    const int gid = l >> 2;
    const int tig = l & 3;

    float d[TPW][4];
#pragma unroll
    for (int u = 0; u < TPW; ++u)
#pragma unroll
        for (int j = 0; j < 4; ++j) d[u][j] = 0.0f;

    const int ebeg = g_off[n];
    const int eend = g_off[n + 1];

    // prefetch first edge's window into buffer 0
    {
        const int s = __ldg(&src[g_elist[ebeg]]);
        const float4* ap = reinterpret_cast<const float4*>(
            g_act + ((size_t)(s * BB + b) * 4 * PLANE + qbase) * 2);
#pragma unroll
        for (int pair = 0; pair < 4; ++pair)
            for (int i = t; i < PAIR4; i += 256)
                cpa16(s_win_u32 + (pair * PSTR2 + i * 4) * 4,
                      ap + pair * (PLANE / 2) + i);
        asm volatile("cp.async.commit_group;");
    }

    for (int ei = ebeg; ei < eend; ++ei) {
        const int p = (ei - ebeg) & 1;
        const int e = g_elist[ei];
        const float esc = g_escale[e];

        // B fragments (overlap with async window copy)
        uint32_t b0r[16], b1r[16];
        {
            const float* wg = weights + (size_t)e * (CC * CC * KK * KK);
            const float4* p0 = reinterpret_cast<const float4*>(wg + ((gid * CC + tig) << 4));
            const float4* p1 = reinterpret_cast<const float4*>(wg + ((gid * CC + tig + 4) << 4));
#pragma unroll
            for (int k4 = 0; k4 < 4; ++k4) {
                float4 v0 = p0[k4];
                float4 v1 = p1[k4];
                b0r[k4 * 4 + 0] = f2tf32(v0.x * esc);
                b0r[k4 * 4 + 1] = f2tf32(v0.y * esc);
                b0r[k4 * 4 + 2] = f2tf32(v0.z * esc);
                b0r[k4 * 4 + 3] = f2tf32(v0.w * esc);
                b1r[k4 * 4 + 0] = f2tf32(v1.x * esc);
                b1r[k4 * 4 + 1] = f2tf32(v1.y * esc);
                b1r[k4 * 4 + 2] = f2tf32(v1.z * esc);
                b1r[k4 * 4 + 3] = f2tf32(v1.w * esc);
            }
        }

        asm volatile("cp.async.wait_group 0;");
        __syncthreads();

        // prefetch next edge's window
        if (ei + 1 < eend) {
            const int s2 = __ldg(&src[g_elist[ei + 1]]);
            const float4* ap2 = reinterpret_cast<const float4*>(
                g_act + ((size_t)(s2 * BB + b) * 4 * PLANE + qbase) * 2);
            const uint32_t dbase = s_win_u32 + (1 - p) * (BUFF * 4);
#pragma unroll
            for (int pair = 0; pair < 4; ++pair)
                for (int i = t; i < PAIR4; i += 256)
                    cpa16(dbase + (pair * PSTR2 + i * 4) * 4,
                          ap2 + pair * (PLANE / 2) + i);
            asm volatile("cp.async.commit_group;");
        }

        // compute on buffer p: taps outer, u inner (independent MMAs)
        const float* fbase = s_win + p * BUFF + tig * PSTR2 + gid * 2;
#pragma unroll
        for (int ky = 0; ky < KK; ++ky) {
#pragma unroll
            for (int kx = 0; kx < KK; ++kx) {
                const int o2 = (ky * PW + kx) * 2;
                const uint32_t bt0 = b0r[ky * 4 + kx];
                const uint32_t bt1 = b1r[ky * 4 + kx];
#pragma unroll
                for (int u = 0; u < TPW; ++u) {
                    const int lq2 = (w * TPW + u) * 32;      // lq*2
                    const float2 v01 = *reinterpret_cast<const float2*>(
                        fbase + lq2 + o2);
                    const float2 v23 = *reinterpret_cast<const float2*>(
                        fbase + lq2 + o2 + 16);
                    mma_tf32(d[u],
                             __float_as_uint(v01.x), __float_as_uint(v23.x),
                             __float_as_uint(v01.y), __float_as_uint(v23.y),
                             bt0, bt1);
                }
            }
        }
    }

    // Epilogue: store future + fused sigmoid sum
    float ls = 0.0f;
    const int co0 = tig * 2;
    float* outn = out + (size_t)((n * BB + b) * CC) * HW;
#pragma unroll
    for (int u = 0; u < TPW; ++u) {
        const int lq = qbase + (w * TPW + u) * 16;
#pragma unroll
        for (int h = 0; h < 2; ++h) {
            const int q = lq + gid + h * 8;
            const int y = q / PW;
            const int x = q - y * PW;
            if (x < WW) {
                float v0 = d[u][h * 2 + 0];
                float v1 = d[u][h * 2 + 1];
                float* ob = outn + y * WW + x;
                ob[(size_t)co0 * HW] = v0;
                ob[(size_t)(co0 + 1) * HW] = v1;
                ls += 1.0f / (1.0f + __expf(-v0));
                ls += 1.0f / (1.0f + __expf(-v1));
            }
        }
    }
#pragma unroll
    for (int o = 16; o > 0; o >>= 1) ls += __shfl_down_sync(0xffffffffu, ls, o);
    if (l == 0) s_red[w] = ls;
    __syncthreads();
    if (t == 0) {
        float sum = 0.0f;
#pragma unroll
        for (int i = 0; i < 8; ++i) sum += s_red[i];
        atomicAdd(&g_postsum[n], sum);
        __threadfence();
        unsigned prev = atomicAdd(&g_done, 1u);
        s_last = (prev == NBLK - 1) ? 1 : 0;
        if (s_last) g_done = 0;
    }
    __syncthreads();
    if (s_last && t < EE) {
        float mean = g_postsum[dst[t]] * (1.0f / (float)BCHW);
        outp[t] = plast[t] + 0.1f * (mean - 0.5f);
    }
}

// ---------------------------------------------------------------------------
extern "C" void kernel_launch(void* const* d_in, const int* in_sizes, int n_in,
                              void* d_out, int out_size) {
    const float* states  = (const float*)d_in[0];
    const float* weights = (const float*)d_in[1];
    const float* plast   = (const float*)d_in[2];
    const int*   src     = (const int*)d_in[3];
    const int*   dst     = (const int*)d_in[4];
    float* out = (float*)d_out;

    dim3 agrid(9, 25 * BB * CC);
    act_prep_kernel<<<agrid, 256>>>(states, dst, plast);

    static int smem_set = 0;
    const int smem_bytes = 2 * BUFF * 4;     // 60672
    if (!smem_set) {
        cudaFuncSetAttribute(conv_mma_kernel,
                             cudaFuncAttributeMaxDynamicSharedMemorySize,
                             smem_bytes);
        smem_set = 1;
    }
    dim3 grid(NSEG, BB, NN);
    conv_mma_kernel<<<grid, 256, smem_bytes>>>(weights, src, plast, dst, out,
                                               out + (out_size - EE));
}

// round 6
// speedup vs baseline: 1.0729x; 1.0729x over previous
#include <cuda_runtime.h>
#include <cstdint>

// Problem constants
#define NN   24
#define EE   96
#define BB   4
#define CC   8
#define HH   96
#define WW   96
#define KK   4
#define HW    (HH*WW)
#define CHW   (CC*HW)
#define BCHW  (BB*CHW)

// Padded activation scratch, ci-pair interleaved:
//   [gp=400][pos<PLANE][half=2]; value(ci,pos) of plane-group g at
//   ((g*4 + (ci&3))*PLANE + pos)*2 + (ci>>2). Zero border (never written).
#define PH 100
#define PW 100
#define PLANE (PH*PW)
#define NACT  (25*BB*4*PLANE*2)

// Conv-MMA tiling
#define SEGPX  640               // pixels per block (40 m16 tiles)
#define NSEG   15
#define TPW    5                 // m16 tiles per warp (8 warps)
#define WINF   944               // window positions per ci
#define PSTR2  1896              // pair stride in floats (==8 mod 32)
#define ABUF   (4*PSTR2)         // 7584 floats: activation window
#define WREG   1024              // weight floats per edge
#define EBUF   (ABUF+WREG)       // 8608 floats per stage buffer
#define PAIR4  472               // float4s per pair window
#define NBLK   (NSEG*BB*NN)      // 1440 conv blocks

__device__ __align__(16) float g_act[NACT];
__device__ int   g_off[NN + 1];
__device__ int   g_elist[EE];
__device__ float g_escale[EE];
__device__ float g_postsum[NN];
__device__ unsigned int g_done;

__device__ __forceinline__ uint32_t f2tf32(float v) {
    uint32_t r;
    asm("cvt.rna.tf32.f32 %0, %1;" : "=r"(r) : "f"(v));
    return r;
}

__device__ __forceinline__ void mma_tf32(float* d, uint32_t a0, uint32_t a1,
                                         uint32_t a2, uint32_t a3,
                                         uint32_t b0, uint32_t b1) {
    asm volatile(
        "mma.sync.aligned.m16n8k8.row.col.f32.tf32.tf32.f32 "
        "{%0,%1,%2,%3}, {%4,%5,%6,%7}, {%8,%9}, {%0,%1,%2,%3};"
        : "+f"(d[0]), "+f"(d[1]), "+f"(d[2]), "+f"(d[3])
        : "r"(a0), "r"(a1), "r"(a2), "r"(a3), "r"(b0), "r"(b1));
}

__device__ __forceinline__ void cpa16(uint32_t dst, const void* src) {
    asm volatile("cp.async.cg.shared.global [%0], [%1], 16;"
                 :: "r"(dst), "l"(src));
}
__device__ __forceinline__ uint32_t smem_u32(const void* p) {
    uint32_t a;
    asm("{ .reg .u64 t; cvta.to.shared.u64 t, %1; cvt.u32.u64 %0, t; }"
        : "=r"(a) : "l"(p));
    return a;
}

// ---------------------------------------------------------------------------
// Activation precompute (+ prep in block (0,0)). grid = (9, 400 pair-planes).
// Each thread: 2 float4 reads (lo/hi plane), 8 sigmoids, 4 coalesced float2
// interleaved writes.
// ---------------------------------------------------------------------------
__global__ __launch_bounds__(256)
void act_prep_kernel(const float* __restrict__ states,
                     const int* __restrict__ dst,
                     const float* __restrict__ plast) {
    const int t = threadIdx.x;
    if (blockIdx.x == 0 && blockIdx.y == 0) {
        __shared__ int cnt[NN];
        __shared__ int fill[NN];
        if (t < NN) { cnt[t] = 0; g_postsum[t] = 0.0f; }
        __syncthreads();
        if (t < EE) atomicAdd(&cnt[dst[t]], 1);
        __syncthreads();
        if (t == 0) {
            int off = 0;
            for (int n = 0; n < NN; ++n) { g_off[n] = off; fill[n] = off; off += cnt[n]; }
            g_off[NN] = off;
        }
        __syncthreads();
        if (t < EE) {
            int d = dst[t];
            int pos = atomicAdd(&fill[d], 1);
            g_elist[pos] = t;
            int deg = cnt[d] > 0 ? cnt[d] : 1;
            g_escale[t] = plast[t] / (float)deg;
        }
    }
    const int gp = blockIdx.y;              // g*4 + pair, 0..399
    const int g = gp >> 2;
    const int pair = gp & 3;
    const int idx4 = blockIdx.x * 256 + t;  // 0..2303
    const int r = idx4 / 24;
    const int c4 = idx4 - r * 24;

    const size_t base = (size_t)(g * CC + pair) * HW + r * WW + c4 * 4;
    const float4 zl = *reinterpret_cast<const float4*>(states + base);
    const float4 zh = *reinterpret_cast<const float4*>(states + base + 4 * HW);

    float l0 = __uint_as_float(f2tf32(1.0f / (1.0f + __expf(-zl.x))));
    float l1 = __uint_as_float(f2tf32(1.0f / (1.0f + __expf(-zl.y))));
    float l2 = __uint_as_float(f2tf32(1.0f / (1.0f + __expf(-zl.z))));
    float l3 = __uint_as_float(f2tf32(1.0f / (1.0f + __expf(-zl.w))));
    float h0 = __uint_as_float(f2tf32(1.0f / (1.0f + __expf(-zh.x))));
    float h1 = __uint_as_float(f2tf32(1.0f / (1.0f + __expf(-zh.y))));
    float h2 = __uint_as_float(f2tf32(1.0f / (1.0f + __expf(-zh.z))));
    float h3 = __uint_as_float(f2tf32(1.0f / (1.0f + __expf(-zh.w))));

    float2* op = reinterpret_cast<float2*>(
        g_act + ((size_t)gp * PLANE + (r + 1) * PW + 1 + c4 * 4) * 2);
    op[0] = make_float2(l0, h0);
    op[1] = make_float2(l1, h1);
    op[2] = make_float2(l2, h2);
    op[3] = make_float2(l3, h3);
}

// ---------------------------------------------------------------------------
// Conv via warp MMA (tf32). Double-buffered cp.async stages window + weights.
// grid = (NSEG, B, N), 256 threads, 3 blocks/SM target.
// ---------------------------------------------------------------------------
extern __shared__ float s_dyn[];

__global__ __launch_bounds__(256, 3)
void conv_mma_kernel(const float* __restrict__ weights,
                     const int* __restrict__ src,
                     const float* __restrict__ plast,
                     const int* __restrict__ dst,
                     float* __restrict__ out,
                     float* __restrict__ outp) {
    const int seg = blockIdx.x;
    const int b = blockIdx.y;
    const int n = blockIdx.z;
    const int qbase = seg * SEGPX;

    __shared__ float s_red[8];
    __shared__ int s_last;
    float* s_win = s_dyn;                          // [2][EBUF]
    const uint32_t s_win_u32 = smem_u32(s_win);

    const int t = threadIdx.x;
    const int w = t >> 5;
    const int l = t & 31;
    const int gid = l >> 2;
    const int tig = l & 3;

    float d[TPW][4];
#pragma unroll
    for (int u = 0; u < TPW; ++u)
#pragma unroll
        for (int j = 0; j < 4; ++j) d[u][j] = 0.0f;

    const int ebeg = g_off[n];
    const int eend = g_off[n + 1];

    // stage edge ei into buffer: activation window (4 pairs) + weight block
    auto stage = [&](int e, uint32_t dbase) {
        const int s = __ldg(&src[e]);
        const float4* ap = reinterpret_cast<const float4*>(
            g_act + ((size_t)(s * BB + b) * 4 * PLANE + qbase) * 2);
#pragma unroll
        for (int pair = 0; pair < 4; ++pair)
            for (int i = t; i < PAIR4; i += 256)
                cpa16(dbase + (pair * PSTR2 + i * 4) * 4,
                      ap + pair * (PLANE / 2) + i);
        const float4* wp = reinterpret_cast<const float4*>(
            weights + (size_t)e * WREG);
        cpa16(dbase + (ABUF + t * 4) * 4, wp + t);   // 256 f4 = 1024 floats
        asm volatile("cp.async.commit_group;");
    };

    stage(g_elist[ebeg], s_win_u32);

    for (int ei = ebeg; ei < eend; ++ei) {
        const int p = (ei - ebeg) & 1;
        const float esc = g_escale[g_elist[ei]];

        asm volatile("cp.async.wait_group 0;");
        __syncthreads();

        if (ei + 1 < eend)
            stage(g_elist[ei + 1], s_win_u32 + (1 - p) * (EBUF * 4));

        // compute on buffer p
        const float* fbase = s_win + p * EBUF + tig * PSTR2 + gid * 2;
        const float* wsm = s_win + p * EBUF + ABUF;
        const int wo0 = (gid * CC + tig) << 4;
        const int wo1 = (gid * CC + tig + 4) << 4;
#pragma unroll
        for (int ky = 0; ky < KK; ++ky) {
            const float4 w0 = *reinterpret_cast<const float4*>(wsm + wo0 + ky * 4);
            const float4 w1 = *reinterpret_cast<const float4*>(wsm + wo1 + ky * 4);
            uint32_t bk0[4], bk1[4];
            bk0[0] = f2tf32(w0.x * esc); bk0[1] = f2tf32(w0.y * esc);
            bk0[2] = f2tf32(w0.z * esc); bk0[3] = f2tf32(w0.w * esc);
            bk1[0] = f2tf32(w1.x * esc); bk1[1] = f2tf32(w1.y * esc);
            bk1[2] = f2tf32(w1.z * esc); bk1[3] = f2tf32(w1.w * esc);
#pragma unroll
            for (int kx = 0; kx < KK; ++kx) {
                const int o2 = (ky * PW + kx) * 2;
#pragma unroll
                for (int u = 0; u < TPW; ++u) {
                    const int lq2 = (w * TPW + u) * 32;
                    const float2 v01 = *reinterpret_cast<const float2*>(
                        fbase + lq2 + o2);
                    const float2 v23 = *reinterpret_cast<const float2*>(
                        fbase + lq2 + o2 + 16);
                    mma_tf32(d[u],
                             __float_as_uint(v01.x), __float_as_uint(v23.x),
                             __float_as_uint(v01.y), __float_as_uint(v23.y),
                             bk0[kx], bk1[kx]);
                }
            }
        }
    }

    // Epilogue: store future + fused sigmoid sum
    float ls = 0.0f;
    const int co0 = tig * 2;
    float* outn = out + (size_t)((n * BB + b) * CC) * HW;
#pragma unroll
    for (int u = 0; u < TPW; ++u) {
        const int lq = qbase + (w * TPW + u) * 16;
#pragma unroll
        for (int h = 0; h < 2; ++h) {
            const int q = lq + gid + h * 8;
            const int y = q / PW;
            const int x = q - y * PW;
            if (x < WW) {
                float v0 = d[u][h * 2 + 0];
                float v1 = d[u][h * 2 + 1];
                float* ob = outn + y * WW + x;
                ob[(size_t)co0 * HW] = v0;
                ob[(size_t)(co0 + 1) * HW] = v1;
                ls += 1.0f / (1.0f + __expf(-v0));
                ls += 1.0f / (1.0f + __expf(-v1));
            }
        }
    }
#pragma unroll
    for (int o = 16; o > 0; o >>= 1) ls += __shfl_down_sync(0xffffffffu, ls, o);
    if (l == 0) s_red[w] = ls;
    __syncthreads();
    if (t == 0) {
        float sum = 0.0f;
#pragma unroll
        for (int i = 0; i < 8; ++i) sum += s_red[i];
        atomicAdd(&g_postsum[n], sum);
        __threadfence();
        unsigned prev = atomicAdd(&g_done, 1u);
        s_last = (prev == NBLK - 1) ? 1 : 0;
        if (s_last) g_done = 0;
    }
    __syncthreads();
    if (s_last && t < EE) {
        float mean = g_postsum[dst[t]] * (1.0f / (float)BCHW);
        outp[t] = plast[t] + 0.1f * (mean - 0.5f);
    }
}

// ---------------------------------------------------------------------------
extern "C" void kernel_launch(void* const* d_in, const int* in_sizes, int n_in,
                              void* d_out, int out_size) {
    const float* states  = (const float*)d_in[0];
    const float* weights = (const float*)d_in[1];
    const float* plast   = (const float*)d_in[2];
    const int*   src     = (const int*)d_in[3];
    const int*   dst     = (const int*)d_in[4];
    float* out = (float*)d_out;

    dim3 agrid(9, 400);
    act_prep_kernel<<<agrid, 256>>>(states, dst, plast);

    static int smem_set = 0;
    const int smem_bytes = 2 * EBUF * 4;     // 68864
    if (!smem_set) {
        cudaFuncSetAttribute(conv_mma_kernel,
                             cudaFuncAttributeMaxDynamicSharedMemorySize,
                             smem_bytes);
        smem_set = 1;
    }
    dim3 grid(NSEG, BB, NN);
    conv_mma_kernel<<<grid, 256, smem_bytes>>>(weights, src, plast, dst, out,
                                               out + (out_size - EE));
}